// round 7
// baseline (speedup 1.0000x reference)
#include <cuda_runtime.h>
#include <cuda_fp16.h>
#include <cuda_pipeline.h>
#include <mma.h>
#include <math.h>

#define TOK   4096
#define DIMC  1024
#define MLPC  4096
#define NSEQ  512
#define HD    64
#define PART  256

#define F_BIAS  1
#define F_GELU  2
#define F_RES   4
#define F_SCALE 8
#define F_OUTF  16
#define F_OUTH  32
#define F_IDX   64

using namespace nvcuda;

/* static device scratch */
__device__ __half g_xn_h [TOK * DIMC];
__device__ __half g_qkv_h[TOK * 3 * DIMC];
__device__ __half g_attn_h[(size_t)128 * NSEQ * NSEQ];
__device__ __half g_ctx_h[TOK * DIMC];
__device__ float  g_x1   [TOK * DIMC];
__device__ __half g_h_h  [TOK * MLPC];
__device__ __half g_qkvw_h[DIMC * 3 * DIMC];
__device__ __half g_outw_h[DIMC * DIMC];
__device__ __half g_fc1w_h[DIMC * MLPC];
__device__ __half g_fc2w_h[MLPC * (DIMC - PART)];
__device__ __half g_expw_h[8 * MLPC * PART];

__device__ __forceinline__ float gelu_f(float v) {
    return 0.5f * v * (1.0f + erff(v * 0.70710678118654752f));
}

/* fp32 to fp16 conversion */
__global__ void cvt_k(const float* __restrict__ in, __half* __restrict__ out, int n4) {
    int i = blockIdx.x * blockDim.x + threadIdx.x;
    if (i < n4) {
        float4 v = reinterpret_cast<const float4*>(in)[i];
        reinterpret_cast<__half2*>(out)[i * 2 + 0] = __floats2half2_rn(v.x, v.y);
        reinterpret_cast<__half2*>(out)[i * 2 + 1] = __floats2half2_rn(v.z, v.w);
    }
}

/* layernorm fp32 in, fp16 out */
__global__ void layernorm_h_k(const float* __restrict__ x,
                              const float* __restrict__ w,
                              const float* __restrict__ b,
                              __half* __restrict__ out) {
    int row = blockIdx.x;
    int t = threadIdx.x;
    float4 v = reinterpret_cast<const float4*>(x + (size_t)row * DIMC)[t];
    float s  = v.x + v.y + v.z + v.w;
    float sq = v.x * v.x + v.y * v.y + v.z * v.z + v.w * v.w;
    #pragma unroll
    for (int o = 16; o > 0; o >>= 1) {
        s  += __shfl_down_sync(0xffffffffu, s,  o);
        sq += __shfl_down_sync(0xffffffffu, sq, o);
    }
    __shared__ float ss[8];
    __shared__ float sq2[8];
    __shared__ float mean_s;
    __shared__ float rstd_s;
    int lane = t & 31;
    int wp = t >> 5;
    if (lane == 0) { ss[wp] = s; sq2[wp] = sq; }
    __syncthreads();
    if (t == 0) {
        float S = 0.f;
        float Q = 0.f;
        #pragma unroll
        for (int i = 0; i < 8; i++) { S += ss[i]; Q += sq2[i]; }
        float m = S * (1.0f / DIMC);
        mean_s = m;
        rstd_s = rsqrtf(Q * (1.0f / DIMC) - m * m + 1e-5f);
    }
    __syncthreads();
    float m = mean_s;
    float r = rstd_s;
    float4 wv = reinterpret_cast<const float4*>(w)[t];
    float4 bv = reinterpret_cast<const float4*>(b)[t];
    float o0 = (v.x - m) * r * wv.x + bv.x;
    float o1 = (v.y - m) * r * wv.y + bv.y;
    float o2 = (v.z - m) * r * wv.z + bv.z;
    float o3 = (v.w - m) * r * wv.w + bv.w;
    __half2* op = reinterpret_cast<__half2*>(out + (size_t)row * DIMC);
    op[t * 2 + 0] = __floats2half2_rn(o0, o1);
    op[t * 2 + 1] = __floats2half2_rn(o2, o3);
}

/* softmax: fp32 in-place plus fp16 copy */
__global__ void softmax_k(float* __restrict__ attn, __half* __restrict__ attn_h) {
    size_t row = blockIdx.x;
    float4* p = reinterpret_cast<float4*>(attn + row * NSEQ);
    int t = threadIdx.x;
    float4 v = p[t];
    float m = fmaxf(fmaxf(v.x, v.y), fmaxf(v.z, v.w));
    #pragma unroll
    for (int o = 16; o > 0; o >>= 1) m = fmaxf(m, __shfl_xor_sync(0xffffffffu, m, o));
    __shared__ float sm[4];
    __shared__ float ssum[4];
    int lane = t & 31;
    int wp = t >> 5;
    if (lane == 0) sm[wp] = m;
    __syncthreads();
    m = fmaxf(fmaxf(sm[0], sm[1]), fmaxf(sm[2], sm[3]));
    float4 e;
    e.x = expf(v.x - m);
    e.y = expf(v.y - m);
    e.z = expf(v.z - m);
    e.w = expf(v.w - m);
    float s = e.x + e.y + e.z + e.w;
    #pragma unroll
    for (int o = 16; o > 0; o >>= 1) s += __shfl_xor_sync(0xffffffffu, s, o);
    if (lane == 0) ssum[wp] = s;
    __syncthreads();
    s = ssum[0] + ssum[1] + ssum[2] + ssum[3];
    float inv = 1.0f / s;
    e.x *= inv;
    e.y *= inv;
    e.z *= inv;
    e.w *= inv;
    p[t] = e;
    __half2* hp = reinterpret_cast<__half2*>(attn_h + row * NSEQ);
    hp[t * 2 + 0] = __floats2half2_rn(e.x, e.y);
    hp[t * 2 + 1] = __floats2half2_rn(e.z, e.w);
}

/* one pipeline stage load: A tile BMx32, B tile (NN: 32xBN, NT: BNx32) */
template<int BM, int BN, int BT>
__device__ __forceinline__ void load_stage(const __half* A, int lda,
                                           const __half* B, int ldb,
                                           int brow, int bcol, int k0,
                                           __half* As, __half* Bs, int tid) {
    const int AP  = 40;
    const int BPN = BN + 8;
    const int BPT = 40;
    #pragma unroll
    for (int rb = 0; rb < BM / 128; rb++) {
        const int lr = rb * 128 + (tid >> 1);
        const int lc = (tid & 1) * 16;
        const __half* ga = A + (long)(brow + lr) * lda + k0 + lc;
        __pipeline_memcpy_async(&As[lr * AP + lc], ga, 16);
        __pipeline_memcpy_async(&As[lr * AP + lc + 8], ga + 8, 16);
    }
    if (BT) {
        const int lr = tid >> 1;
        const int lc = (tid & 1) * 16;
        if (lr < BN) {
            const __half* gb = B + (long)(bcol + lr) * ldb + k0 + lc;
            __pipeline_memcpy_async(&Bs[lr * BPT + lc], gb, 16);
            __pipeline_memcpy_async(&Bs[lr * BPT + lc + 8], gb + 8, 16);
        }
    } else {
        const int CH = BN / 8;
        #pragma unroll
        for (int q = 0; q < (32 * CH + 255) / 256; q++) {
            const int idx = tid + q * 256;
            if (idx < 32 * CH) {
                const int r = idx / CH;
                const int c = idx % CH;
                __pipeline_memcpy_async(&Bs[r * BPN + c * 8],
                                        B + (long)(k0 + r) * ldb + bcol + c * 8, 16);
            }
        }
    }
}

/*
 * WMMA tensor-core GEMM. Block tile BM x BN, K-step 32, 3-stage cp.async
 * pipeline in dynamic shared memory. 8 warps as 4(m) x 2(n): each warp owns
 * (BM/4) x (BN/2). BT=1 means B is [N,K] row-major. Batched over blockIdx.z
 * decomposed as (z>>4, z&15) with explicit strides.
 */
template<int BM, int BN, int FLAGS, int BT>
__global__ __launch_bounds__(256, (BM == 256) ? 1 : 2)
void hgemm(const __half* __restrict__ A, int lda,
           const __half* __restrict__ B, int ldb,
           float* __restrict__ Cf, __half* __restrict__ Ch, int ldc,
           int K,
           const float* __restrict__ bias,
           const float* __restrict__ res, int ldr,
           float scale,
           const int* __restrict__ indices, long wstride, int bstride,
           long za1, long za2, long zb1, long zb2, long zc1, long zc2)
{
    const int z = blockIdx.z;
    const int zb = z >> 4;
    const int zh = z & 15;
    A += (long)zb * za1 + (long)zh * za2;
    B += (long)zb * zb1 + (long)zh * zb2;
    const long coff = (long)zb * zc1 + (long)zh * zc2;
    if (FLAGS & F_IDX) {
        int idx = indices[(blockIdx.y * BM) >> 9];
        B    += (long)idx * wstride;
        bias += (long)idx * bstride;
    }
    const int brow = blockIdx.y * BM;
    const int bcol = blockIdx.x * BN;

    constexpr int AP  = 40;
    constexpr int BPN = BN + 8;
    constexpr int BPT = 40;
    constexpr int ASZ = BM * AP;
    constexpr int BSZ = BT ? (BN * BPT) : (32 * BPN);

    extern __shared__ __align__(16) char dyn[];
    __half* As = reinterpret_cast<__half*>(dyn);
    __half* Bs = As + 3 * ASZ;

    const int tid  = threadIdx.x;
    const int warp = tid >> 5;
    const int lane = tid & 31;
    const int wm = warp & 3;
    const int wn = warp >> 2;
    constexpr int MTF = BM / 64;       /* 16-row frags per warp row */
    constexpr int NTF = BN / 32;       /* 16-col frags per warp col */

    wmma::fragment<wmma::accumulator, 16, 16, 16, float> acc[MTF][NTF];
    #pragma unroll
    for (int i = 0; i < MTF; i++) {
        #pragma unroll
        for (int j = 0; j < NTF; j++) wmma::fill_fragment(acc[i][j], 0.0f);
    }

    const int iters = K >> 5;

    load_stage<BM, BN, BT>(A, lda, B, ldb, brow, bcol, 0, As, Bs, tid);
    __pipeline_commit();
    if (iters > 1) {
        load_stage<BM, BN, BT>(A, lda, B, ldb, brow, bcol, 32, As + ASZ, Bs + BSZ, tid);
        __pipeline_commit();
    }

    for (int it = 0; it < iters; ++it) {
        if (it + 1 < iters) {
            __pipeline_wait_prior(1);
        } else {
            __pipeline_wait_prior(0);
        }
        __syncthreads();
        if (it + 2 < iters) {
            const int ns = (it + 2) % 3;
            load_stage<BM, BN, BT>(A, lda, B, ldb, brow, bcol, (it + 2) * 32,
                                   As + ns * ASZ, Bs + ns * BSZ, tid);
            __pipeline_commit();
        }
        const int slot = it % 3;

        #pragma unroll
        for (int ks = 0; ks < 32; ks += 16) {
            wmma::fragment<wmma::matrix_a, 16, 16, 16, __half, wmma::row_major> af[MTF];
            #pragma unroll
            for (int mt = 0; mt < MTF; mt++) {
                const __half* ap = &As[slot * ASZ + (wm * (BM / 4) + mt * 16) * AP + ks];
                wmma::load_matrix_sync(af[mt], ap, AP);
            }
            if (BT) {
                wmma::fragment<wmma::matrix_b, 16, 16, 16, __half, wmma::col_major> bf[NTF];
                #pragma unroll
                for (int nt = 0; nt < NTF; nt++) {
                    const __half* bp = &Bs[slot * BSZ + (wn * (BN / 2) + nt * 16) * BPT + ks];
                    wmma::load_matrix_sync(bf[nt], bp, BPT);
                }
                #pragma unroll
                for (int mt = 0; mt < MTF; mt++) {
                    #pragma unroll
                    for (int nt = 0; nt < NTF; nt++) {
                        wmma::mma_sync(acc[mt][nt], af[mt], bf[nt], acc[mt][nt]);
                    }
                }
            } else {
                wmma::fragment<wmma::matrix_b, 16, 16, 16, __half, wmma::row_major> bf[NTF];
                #pragma unroll
                for (int nt = 0; nt < NTF; nt++) {
                    const __half* bp = &Bs[slot * BSZ + ks * BPN + wn * (BN / 2) + nt * 16];
                    wmma::load_matrix_sync(bf[nt], bp, BPN);
                }
                #pragma unroll
                for (int mt = 0; mt < MTF; mt++) {
                    #pragma unroll
                    for (int nt = 0; nt < NTF; nt++) {
                        wmma::mma_sync(acc[mt][nt], af[mt], bf[nt], acc[mt][nt]);
                    }
                }
            }
        }
    }

    __syncthreads();

    /* epilogue: stage each 16x16 accumulator through smem */
    float* stage = reinterpret_cast<float*>(dyn) + warp * 16 * 20;
    const int er = lane >> 1;
    const int ec = (lane & 1) * 8;
    #pragma unroll
    for (int mt = 0; mt < MTF; mt++) {
        #pragma unroll
        for (int nt = 0; nt < NTF; nt++) {
            wmma::store_matrix_sync(stage, acc[mt][nt], 20, wmma::mem_row_major);
            __syncwarp();
            const int row = brow + wm * (BM / 4) + mt * 16 + er;
            const int col = bcol + wn * (BN / 2) + nt * 16 + ec;
            float v[8];
            #pragma unroll
            for (int j = 0; j < 8; j++) v[j] = stage[er * 20 + ec + j];
            if (FLAGS & F_SCALE) {
                #pragma unroll
                for (int j = 0; j < 8; j++) v[j] *= scale;
            }
            if (FLAGS & F_BIAS) {
                #pragma unroll
                for (int j = 0; j < 8; j++) v[j] += bias[col + j];
            }
            if (FLAGS & F_GELU) {
                #pragma unroll
                for (int j = 0; j < 8; j++) v[j] = gelu_f(v[j]);
            }
            if (FLAGS & F_RES) {
                #pragma unroll
                for (int j = 0; j < 8; j++) v[j] += res[(long)row * ldr + col + j];
            }
            const long off = coff + (long)row * ldc + col;
            if (FLAGS & F_OUTF) {
                float4 f0;
                f0.x = v[0]; f0.y = v[1]; f0.z = v[2]; f0.w = v[3];
                float4 f1;
                f1.x = v[4]; f1.y = v[5]; f1.z = v[6]; f1.w = v[7];
                *reinterpret_cast<float4*>(&Cf[off]) = f0;
                *reinterpret_cast<float4*>(&Cf[off + 4]) = f1;
            }
            if (FLAGS & F_OUTH) {
                __half2* hp = reinterpret_cast<__half2*>(&Ch[off]);
                hp[0] = __floats2half2_rn(v[0], v[1]);
                hp[1] = __floats2half2_rn(v[2], v[3]);
                hp[2] = __floats2half2_rn(v[4], v[5]);
                hp[3] = __floats2half2_rn(v[6], v[7]);
            }
            __syncwarp();
        }
    }
}

/* dynamic smem byte counts per instantiation */
#define SMEM_NN128 (3 * (128 * 40 + 32 * 136) * 2)
#define SMEM_NN256 (3 * (256 * 40 + 32 * 136) * 2)
#define SMEM_BT128 (3 * (128 * 40 + 128 * 40) * 2)
#define SMEM_NN64  (3 * (128 * 40 + 32 * 72) * 2)

extern "C" void kernel_launch(void* const* d_in, const int* in_sizes, int n_in,
                              void* d_out, int out_size) {
    const float* x       = (const float*)d_in[0];
    const int*   indices = (const int*)  d_in[1];
    const float* ln1_w   = (const float*)d_in[2];
    const float* ln1_b   = (const float*)d_in[3];
    const float* qkv_w   = (const float*)d_in[4];
    const float* qkv_b   = (const float*)d_in[5];
    const float* out_w   = (const float*)d_in[6];
    const float* out_b   = (const float*)d_in[7];
    const float* ln2_w   = (const float*)d_in[8];
    const float* ln2_b   = (const float*)d_in[9];
    const float* fc1_w   = (const float*)d_in[10];
    const float* fc1_b   = (const float*)d_in[11];
    const float* fc2_w   = (const float*)d_in[12];
    const float* fc2_b   = (const float*)d_in[13];
    const float* exp_w   = (const float*)d_in[14];
    const float* exp_b   = (const float*)d_in[15];

    float* out_final = (float*)d_out;
    float* attn      = out_final + (size_t)TOK * DIMC;

    void* p;
    cudaGetSymbolAddress(&p, g_xn_h);
    __half* xn_h = (__half*)p;
    cudaGetSymbolAddress(&p, g_qkv_h);
    __half* qkv_h = (__half*)p;
    cudaGetSymbolAddress(&p, g_attn_h);
    __half* attn_h = (__half*)p;
    cudaGetSymbolAddress(&p, g_ctx_h);
    __half* ctx_h = (__half*)p;
    cudaGetSymbolAddress(&p, g_x1);
    float* x1 = (float*)p;
    cudaGetSymbolAddress(&p, g_h_h);
    __half* h_h = (__half*)p;
    cudaGetSymbolAddress(&p, g_qkvw_h);
    __half* qkvw_h = (__half*)p;
    cudaGetSymbolAddress(&p, g_outw_h);
    __half* outw_h = (__half*)p;
    cudaGetSymbolAddress(&p, g_fc1w_h);
    __half* fc1w_h = (__half*)p;
    cudaGetSymbolAddress(&p, g_fc2w_h);
    __half* fc2w_h = (__half*)p;
    cudaGetSymbolAddress(&p, g_expw_h);
    __half* expw_h = (__half*)p;

    cudaFuncSetAttribute(hgemm<256, 128, F_BIAS | F_OUTH, 0>,
                         cudaFuncAttributeMaxDynamicSharedMemorySize, SMEM_NN256);
    cudaFuncSetAttribute(hgemm<128, 128, F_SCALE | F_OUTF, 1>,
                         cudaFuncAttributeMaxDynamicSharedMemorySize, SMEM_BT128);
    cudaFuncSetAttribute(hgemm<128, 64, F_OUTH, 0>,
                         cudaFuncAttributeMaxDynamicSharedMemorySize, SMEM_NN64);
    cudaFuncSetAttribute(hgemm<256, 128, F_BIAS | F_RES | F_OUTF, 0>,
                         cudaFuncAttributeMaxDynamicSharedMemorySize, SMEM_NN256);
    cudaFuncSetAttribute(hgemm<256, 128, F_BIAS | F_GELU | F_OUTH, 0>,
                         cudaFuncAttributeMaxDynamicSharedMemorySize, SMEM_NN256);
    cudaFuncSetAttribute(hgemm<128, 128, F_BIAS | F_RES | F_OUTF, 0>,
                         cudaFuncAttributeMaxDynamicSharedMemorySize, SMEM_NN128);
    cudaFuncSetAttribute(hgemm<128, 128, F_BIAS | F_RES | F_OUTF | F_IDX, 0>,
                         cudaFuncAttributeMaxDynamicSharedMemorySize, SMEM_NN128);

    int n;
    n = DIMC * 3 * DIMC / 4;
    cvt_k<<<(n + 255) / 256, 256>>>(qkv_w, qkvw_h, n);
    n = DIMC * DIMC / 4;
    cvt_k<<<(n + 255) / 256, 256>>>(out_w, outw_h, n);
    n = DIMC * MLPC / 4;
    cvt_k<<<(n + 255) / 256, 256>>>(fc1_w, fc1w_h, n);
    n = MLPC * (DIMC - PART) / 4;
    cvt_k<<<(n + 255) / 256, 256>>>(fc2_w, fc2w_h, n);
    n = 8 * MLPC * PART / 4;
    cvt_k<<<(n + 255) / 256, 256>>>(exp_w, expw_h, n);

    layernorm_h_k<<<TOK, 256>>>(x, ln1_w, ln1_b, xn_h);

    hgemm<256, 128, F_BIAS | F_OUTH, 0><<<dim3(24, 16, 1), 256, SMEM_NN256>>>(
        xn_h, DIMC, qkvw_h, 3 * DIMC, nullptr, qkv_h, 3 * DIMC, DIMC,
        qkv_b, nullptr, 0, 0.f, nullptr, 0, 0,
        0L, 0L, 0L, 0L, 0L, 0L);

    hgemm<128, 128, F_SCALE | F_OUTF, 1><<<dim3(4, 4, 128), 256, SMEM_BT128>>>(
        qkv_h, 3 * DIMC, qkv_h + DIMC, 3 * DIMC, attn, nullptr, NSEQ, HD,
        nullptr, nullptr, 0, 0.03125f, nullptr, 0, 0,
        (long)NSEQ * 3 * DIMC, (long)HD,
        (long)NSEQ * 3 * DIMC, (long)HD,
        16L * NSEQ * NSEQ, (long)NSEQ * NSEQ);

    softmax_k<<<128 * NSEQ, 128>>>(attn, attn_h);

    hgemm<128, 64, F_OUTH, 0><<<dim3(1, 4, 128), 256, SMEM_NN64>>>(
        attn_h, NSEQ, qkv_h + 2 * DIMC, 3 * DIMC, nullptr, ctx_h, DIMC, NSEQ,
        nullptr, nullptr, 0, 0.f, nullptr, 0, 0,
        16L * NSEQ * NSEQ, (long)NSEQ * NSEQ,
        (long)NSEQ * 3 * DIMC, (long)HD,
        (long)NSEQ * DIMC, (long)HD);

    hgemm<256, 128, F_BIAS | F_RES | F_OUTF, 0><<<dim3(8, 16, 1), 256, SMEM_NN256>>>(
        ctx_h, DIMC, outw_h, DIMC, x1, nullptr, DIMC, DIMC,
        out_b, x, DIMC, 0.f, nullptr, 0, 0,
        0L, 0L, 0L, 0L, 0L, 0L);

    layernorm_h_k<<<TOK, 256>>>(x1, ln2_w, ln2_b, xn_h);

    hgemm<256, 128, F_BIAS | F_GELU | F_OUTH, 0><<<dim3(32, 16, 1), 256, SMEM_NN256>>>(
        xn_h, DIMC, fc1w_h, MLPC, nullptr, h_h, MLPC, DIMC,
        fc1_b, nullptr, 0, 0.f, nullptr, 0, 0,
        0L, 0L, 0L, 0L, 0L, 0L);

    hgemm<128, 128, F_BIAS | F_RES | F_OUTF, 0><<<dim3(6, 32, 1), 256, SMEM_NN128>>>(
        h_h, MLPC, fc2w_h, DIMC - PART, out_final, nullptr, DIMC, MLPC,
        fc2_b, x1, DIMC, 0.f, nullptr, 0, 0,
        0L, 0L, 0L, 0L, 0L, 0L);

    hgemm<128, 128, F_BIAS | F_RES | F_OUTF | F_IDX, 0><<<dim3(2, 32, 1), 256, SMEM_NN128>>>(
        h_h, MLPC, expw_h, PART, out_final + (DIMC - PART), nullptr, DIMC, MLPC,
        exp_b, x1 + (DIMC - PART), DIMC, 0.f,
        indices, (long)MLPC * PART, PART,
        0L, 0L, 0L, 0L, 0L, 0L);
}

// round 8
// speedup vs baseline: 1.2364x; 1.2364x over previous
#include <cuda_runtime.h>
#include <cuda_fp16.h>
#include <cuda_pipeline.h>
#include <mma.h>
#include <math.h>

#define TOK   4096
#define DIMC  1024
#define MLPC  4096
#define NSEQ  512
#define HD    64
#define PART  256

#define F_BIAS  1
#define F_GELU  2
#define F_RES   4
#define F_SCALE 8
#define F_OUTF  16
#define F_OUTH  32
#define F_FUSE  64

using namespace nvcuda;

/* static device scratch */
__device__ __half g_xn_h [TOK * DIMC];
__device__ __half g_qkv_h[TOK * 3 * DIMC];
__device__ __half g_attn_h[(size_t)128 * NSEQ * NSEQ];
__device__ __half g_ctx_h[TOK * DIMC];
__device__ float  g_x1   [TOK * DIMC];
__device__ __half g_h_h  [TOK * MLPC];
__device__ __half g_qkvw_h[DIMC * 3 * DIMC];
__device__ __half g_outw_h[DIMC * DIMC];
__device__ __half g_fc1w_h[DIMC * MLPC];
__device__ __half g_fc2w_h[MLPC * (DIMC - PART)];
__device__ __half g_expw_h[8 * MLPC * PART];

__device__ __forceinline__ float gelu_f(float v) {
    return 0.5f * v * (1.0f + erff(v * 0.70710678118654752f));
}

/* fused fp32 to fp16 conversion over five weight tensors */
__global__ void cvt5_k(const float* __restrict__ w0, __half* __restrict__ o0, int n0,
                       const float* __restrict__ w1, __half* __restrict__ o1, int n1,
                       const float* __restrict__ w2, __half* __restrict__ o2, int n2,
                       const float* __restrict__ w3, __half* __restrict__ o3, int n3,
                       const float* __restrict__ w4, __half* __restrict__ o4, int n4) {
    int i = blockIdx.x * blockDim.x + threadIdx.x;
    const float* in;
    __half* out;
    if (i < n0) {
        in = w0; out = o0;
    } else if (i < n0 + n1) {
        i -= n0; in = w1; out = o1;
    } else if (i < n0 + n1 + n2) {
        i -= n0 + n1; in = w2; out = o2;
    } else if (i < n0 + n1 + n2 + n3) {
        i -= n0 + n1 + n2; in = w3; out = o3;
    } else if (i < n0 + n1 + n2 + n3 + n4) {
        i -= n0 + n1 + n2 + n3; in = w4; out = o4;
    } else {
        return;
    }
    float4 v = reinterpret_cast<const float4*>(in)[i];
    reinterpret_cast<__half2*>(out)[i * 2 + 0] = __floats2half2_rn(v.x, v.y);
    reinterpret_cast<__half2*>(out)[i * 2 + 1] = __floats2half2_rn(v.z, v.w);
}

/* layernorm fp32 in, fp16 out */
__global__ void layernorm_h_k(const float* __restrict__ x,
                              const float* __restrict__ w,
                              const float* __restrict__ b,
                              __half* __restrict__ out) {
    int row = blockIdx.x;
    int t = threadIdx.x;
    float4 v = reinterpret_cast<const float4*>(x + (size_t)row * DIMC)[t];
    float s  = v.x + v.y + v.z + v.w;
    float sq = v.x * v.x + v.y * v.y + v.z * v.z + v.w * v.w;
    #pragma unroll
    for (int o = 16; o > 0; o >>= 1) {
        s  += __shfl_down_sync(0xffffffffu, s,  o);
        sq += __shfl_down_sync(0xffffffffu, sq, o);
    }
    __shared__ float ss[8];
    __shared__ float sq2[8];
    __shared__ float mean_s;
    __shared__ float rstd_s;
    int lane = t & 31;
    int wp = t >> 5;
    if (lane == 0) { ss[wp] = s; sq2[wp] = sq; }
    __syncthreads();
    if (t == 0) {
        float S = 0.f;
        float Q = 0.f;
        #pragma unroll
        for (int i = 0; i < 8; i++) { S += ss[i]; Q += sq2[i]; }
        float m = S * (1.0f / DIMC);
        mean_s = m;
        rstd_s = rsqrtf(Q * (1.0f / DIMC) - m * m + 1e-5f);
    }
    __syncthreads();
    float m = mean_s;
    float r = rstd_s;
    float4 wv = reinterpret_cast<const float4*>(w)[t];
    float4 bv = reinterpret_cast<const float4*>(b)[t];
    float o0 = (v.x - m) * r * wv.x + bv.x;
    float o1 = (v.y - m) * r * wv.y + bv.y;
    float o2 = (v.z - m) * r * wv.z + bv.z;
    float o3 = (v.w - m) * r * wv.w + bv.w;
    __half2* op = reinterpret_cast<__half2*>(out + (size_t)row * DIMC);
    op[t * 2 + 0] = __floats2half2_rn(o0, o1);
    op[t * 2 + 1] = __floats2half2_rn(o2, o3);
}

/* softmax: fp32 in-place plus fp16 copy */
__global__ void softmax_k(float* __restrict__ attn, __half* __restrict__ attn_h) {
    size_t row = blockIdx.x;
    float4* p = reinterpret_cast<float4*>(attn + row * NSEQ);
    int t = threadIdx.x;
    float4 v = p[t];
    float m = fmaxf(fmaxf(v.x, v.y), fmaxf(v.z, v.w));
    #pragma unroll
    for (int o = 16; o > 0; o >>= 1) m = fmaxf(m, __shfl_xor_sync(0xffffffffu, m, o));
    __shared__ float sm[4];
    __shared__ float ssum[4];
    int lane = t & 31;
    int wp = t >> 5;
    if (lane == 0) sm[wp] = m;
    __syncthreads();
    m = fmaxf(fmaxf(sm[0], sm[1]), fmaxf(sm[2], sm[3]));
    float4 e;
    e.x = expf(v.x - m);
    e.y = expf(v.y - m);
    e.z = expf(v.z - m);
    e.w = expf(v.w - m);
    float s = e.x + e.y + e.z + e.w;
    #pragma unroll
    for (int o = 16; o > 0; o >>= 1) s += __shfl_xor_sync(0xffffffffu, s, o);
    if (lane == 0) ssum[wp] = s;
    __syncthreads();
    s = ssum[0] + ssum[1] + ssum[2] + ssum[3];
    float inv = 1.0f / s;
    e.x *= inv;
    e.y *= inv;
    e.z *= inv;
    e.w *= inv;
    p[t] = e;
    __half2* hp = reinterpret_cast<__half2*>(attn_h + row * NSEQ);
    hp[t * 2 + 0] = __floats2half2_rn(e.x, e.y);
    hp[t * 2 + 1] = __floats2half2_rn(e.z, e.w);
}

/* one pipeline stage load: A tile 128x32, B tile (NN: 32xBN, NT: BNx32).
   Bp is pre-offset to the block's column (NN) or row (BT) start. */
template<int BN, int BT>
__device__ __forceinline__ void load_stage(const __half* A, int lda,
                                           const __half* Bp, long ldbv,
                                           int brow, int k0,
                                           __half* As, __half* Bs, int tid) {
    const int AP  = 40;
    const int BPN = BN + 8;
    const int BPT = 40;
    const int lr = tid >> 1;
    const int lc = (tid & 1) * 16;
    const __half* ga = A + (long)(brow + lr) * lda + k0 + lc;
    __pipeline_memcpy_async(&As[lr * AP + lc], ga, 16);
    __pipeline_memcpy_async(&As[lr * AP + lc + 8], ga + 8, 16);
    if (BT) {
        if (lr < BN) {
            const __half* gb = Bp + (long)lr * ldbv + k0 + lc;
            __pipeline_memcpy_async(&Bs[lr * BPT + lc], gb, 16);
            __pipeline_memcpy_async(&Bs[lr * BPT + lc + 8], gb + 8, 16);
        }
    } else {
        const int CH = BN / 8;
        #pragma unroll
        for (int q = 0; q < (32 * CH + 255) / 256; q++) {
            const int idx = tid + q * 256;
            if (idx < 32 * CH) {
                const int r = idx / CH;
                const int c = idx % CH;
                __pipeline_memcpy_async(&Bs[r * BPN + c * 8],
                                        Bp + (long)(k0 + r) * ldbv + c * 8, 16);
            }
        }
    }
}

/*
 * WMMA tensor-core GEMM. Block tile 128 x BN, K-step 32, 3-stage cp.async
 * pipeline in dynamic shared memory. 8 warps as 4(m) x 2(n): each warp owns
 * 32 x BN/2. BT=1 means B is [N,K] row-major. Batched over blockIdx.z
 * decomposed as (z>>4, z&15) with explicit strides. F_FUSE: column blocks at
 * or beyond DIMC-PART read the per-batch expert weight B2/bias2 instead.
 */
template<int BN, int FLAGS, int BT>
__global__ __launch_bounds__(256, 2)
void hgemm(const __half* __restrict__ A, int lda,
           const __half* __restrict__ B, int ldb,
           float* __restrict__ Cf, __half* __restrict__ Ch, int ldc,
           int K,
           const float* __restrict__ bias,
           const float* __restrict__ res, int ldr,
           float scale,
           const int* __restrict__ indices, long wstride, int bstride,
           const __half* __restrict__ B2, int ldb2,
           const float* __restrict__ bias2,
           long za1, long za2, long zb1, long zb2, long zc1, long zc2)
{
    const int z = blockIdx.z;
    const int zb = z >> 4;
    const int zh = z & 15;
    A += (long)zb * za1 + (long)zh * za2;
    B += (long)zb * zb1 + (long)zh * zb2;
    const long coff = (long)zb * zc1 + (long)zh * zc2;
    const int brow = blockIdx.y * 128;
    const int bcol = blockIdx.x * BN;

    const __half* Bp;
    const float* biasp;
    long ldbv = ldb;
    if (BT) {
        Bp = B + (long)bcol * ldb;
    } else {
        Bp = B + bcol;
    }
    biasp = (FLAGS & F_BIAS) ? (bias + bcol) : bias;
    if ((FLAGS & F_FUSE) && bcol >= (DIMC - PART)) {
        const int idx = indices[brow >> 9];
        Bp    = B2 + (long)idx * wstride + (bcol - (DIMC - PART));
        biasp = bias2 + (long)idx * bstride + (bcol - (DIMC - PART));
        ldbv  = ldb2;
    }

    constexpr int AP  = 40;
    constexpr int BPN = BN + 8;
    constexpr int BPT = 40;
    constexpr int ASZ = 128 * AP;
    constexpr int BSZ = BT ? (BN * BPT) : (32 * BPN);

    extern __shared__ __align__(16) char dyn[];
    __half* As = reinterpret_cast<__half*>(dyn);
    __half* Bs = As + 3 * ASZ;

    const int tid  = threadIdx.x;
    const int warp = tid >> 5;
    const int lane = tid & 31;
    const int wm = warp & 3;
    const int wn = warp >> 2;
    constexpr int NTF = BN / 32;

    wmma::fragment<wmma::accumulator, 16, 16, 16, float> acc[2][NTF];
    #pragma unroll
    for (int i = 0; i < 2; i++) {
        #pragma unroll
        for (int j = 0; j < NTF; j++) wmma::fill_fragment(acc[i][j], 0.0f);
    }

    const int iters = K >> 5;

    load_stage<BN, BT>(A, lda, Bp, ldbv, brow, 0, As, Bs, tid);
    __pipeline_commit();
    if (iters > 1) {
        load_stage<BN, BT>(A, lda, Bp, ldbv, brow, 32, As + ASZ, Bs + BSZ, tid);
        __pipeline_commit();
    }

    for (int it = 0; it < iters; ++it) {
        if (it + 1 < iters) {
            __pipeline_wait_prior(1);
        } else {
            __pipeline_wait_prior(0);
        }
        __syncthreads();
        if (it + 2 < iters) {
            const int ns = (it + 2) % 3;
            load_stage<BN, BT>(A, lda, Bp, ldbv, brow, (it + 2) * 32,
                               As + ns * ASZ, Bs + ns * BSZ, tid);
            __pipeline_commit();
        }
        const int slot = it % 3;

        #pragma unroll
        for (int ks = 0; ks < 32; ks += 16) {
            wmma::fragment<wmma::matrix_a, 16, 16, 16, __half, wmma::row_major> af[2];
            #pragma unroll
            for (int mt = 0; mt < 2; mt++) {
                const __half* ap = &As[slot * ASZ + (wm * 32 + mt * 16) * AP + ks];
                wmma::load_matrix_sync(af[mt], ap, AP);
            }
            if (BT) {
                wmma::fragment<wmma::matrix_b, 16, 16, 16, __half, wmma::col_major> bf[NTF];
                #pragma unroll
                for (int nt = 0; nt < NTF; nt++) {
                    const __half* bp = &Bs[slot * BSZ + (wn * (BN / 2) + nt * 16) * BPT + ks];
                    wmma::load_matrix_sync(bf[nt], bp, BPT);
                }
                #pragma unroll
                for (int mt = 0; mt < 2; mt++) {
                    #pragma unroll
                    for (int nt = 0; nt < NTF; nt++) {
                        wmma::mma_sync(acc[mt][nt], af[mt], bf[nt], acc[mt][nt]);
                    }
                }
            } else {
                wmma::fragment<wmma::matrix_b, 16, 16, 16, __half, wmma::row_major> bf[NTF];
                #pragma unroll
                for (int nt = 0; nt < NTF; nt++) {
                    const __half* bp = &Bs[slot * BSZ + ks * BPN + wn * (BN / 2) + nt * 16];
                    wmma::load_matrix_sync(bf[nt], bp, BPN);
                }
                #pragma unroll
                for (int mt = 0; mt < 2; mt++) {
                    #pragma unroll
                    for (int nt = 0; nt < NTF; nt++) {
                        wmma::mma_sync(acc[mt][nt], af[mt], bf[nt], acc[mt][nt]);
                    }
                }
            }
        }
    }

    __syncthreads();

    /* epilogue: stage each 16x16 accumulator through smem */
    float* stage = reinterpret_cast<float*>(dyn) + warp * 16 * 20;
    const int er = lane >> 1;
    const int ec = (lane & 1) * 8;
    #pragma unroll
    for (int mt = 0; mt < 2; mt++) {
        #pragma unroll
        for (int nt = 0; nt < NTF; nt++) {
            wmma::store_matrix_sync(stage, acc[mt][nt], 20, wmma::mem_row_major);
            __syncwarp();
            const int row = brow + wm * 32 + mt * 16 + er;
            const int lcol = wn * (BN / 2) + nt * 16 + ec;
            const int col = bcol + lcol;
            float v[8];
            #pragma unroll
            for (int j = 0; j < 8; j++) v[j] = stage[er * 20 + ec + j];
            if (FLAGS & F_SCALE) {
                #pragma unroll
                for (int j = 0; j < 8; j++) v[j] *= scale;
            }
            if (FLAGS & F_BIAS) {
                #pragma unroll
                for (int j = 0; j < 8; j++) v[j] += biasp[lcol + j];
            }
            if (FLAGS & F_GELU) {
                #pragma unroll
                for (int j = 0; j < 8; j++) v[j] = gelu_f(v[j]);
            }
            if (FLAGS & F_RES) {
                #pragma unroll
                for (int j = 0; j < 8; j++) v[j] += res[(long)row * ldr + col + j];
            }
            const long off = coff + (long)row * ldc + col;
            if (FLAGS & F_OUTF) {
                float4 f0;
                f0.x = v[0]; f0.y = v[1]; f0.z = v[2]; f0.w = v[3];
                float4 f1;
                f1.x = v[4]; f1.y = v[5]; f1.z = v[6]; f1.w = v[7];
                *reinterpret_cast<float4*>(&Cf[off]) = f0;
                *reinterpret_cast<float4*>(&Cf[off + 4]) = f1;
            }
            if (FLAGS & F_OUTH) {
                __half2* hp = reinterpret_cast<__half2*>(&Ch[off]);
                hp[0] = __floats2half2_rn(v[0], v[1]);
                hp[1] = __floats2half2_rn(v[2], v[3]);
                hp[2] = __floats2half2_rn(v[4], v[5]);
                hp[3] = __floats2half2_rn(v[6], v[7]);
            }
            __syncwarp();
        }
    }
}

/* dynamic smem byte counts per instantiation */
#define SMEM_NN128 (3 * (128 * 40 + 32 * 136) * 2)
#define SMEM_BT128 (3 * (128 * 40 + 128 * 40) * 2)
#define SMEM_NN64  (3 * (128 * 40 + 32 * 72) * 2)

extern "C" void kernel_launch(void* const* d_in, const int* in_sizes, int n_in,
                              void* d_out, int out_size) {
    const float* x       = (const float*)d_in[0];
    const int*   indices = (const int*)  d_in[1];
    const float* ln1_w   = (const float*)d_in[2];
    const float* ln1_b   = (const float*)d_in[3];
    const float* qkv_w   = (const float*)d_in[4];
    const float* qkv_b   = (const float*)d_in[5];
    const float* out_w   = (const float*)d_in[6];
    const float* out_b   = (const float*)d_in[7];
    const float* ln2_w   = (const float*)d_in[8];
    const float* ln2_b   = (const float*)d_in[9];
    const float* fc1_w   = (const float*)d_in[10];
    const float* fc1_b   = (const float*)d_in[11];
    const float* fc2_w   = (const float*)d_in[12];
    const float* fc2_b   = (const float*)d_in[13];
    const float* exp_w   = (const float*)d_in[14];
    const float* exp_b   = (const float*)d_in[15];

    float* out_final = (float*)d_out;
    float* attn      = out_final + (size_t)TOK * DIMC;

    void* p;
    cudaGetSymbolAddress(&p, g_xn_h);
    __half* xn_h = (__half*)p;
    cudaGetSymbolAddress(&p, g_qkv_h);
    __half* qkv_h = (__half*)p;
    cudaGetSymbolAddress(&p, g_attn_h);
    __half* attn_h = (__half*)p;
    cudaGetSymbolAddress(&p, g_ctx_h);
    __half* ctx_h = (__half*)p;
    cudaGetSymbolAddress(&p, g_x1);
    float* x1 = (float*)p;
    cudaGetSymbolAddress(&p, g_h_h);
    __half* h_h = (__half*)p;
    cudaGetSymbolAddress(&p, g_qkvw_h);
    __half* qkvw_h = (__half*)p;
    cudaGetSymbolAddress(&p, g_outw_h);
    __half* outw_h = (__half*)p;
    cudaGetSymbolAddress(&p, g_fc1w_h);
    __half* fc1w_h = (__half*)p;
    cudaGetSymbolAddress(&p, g_fc2w_h);
    __half* fc2w_h = (__half*)p;
    cudaGetSymbolAddress(&p, g_expw_h);
    __half* expw_h = (__half*)p;

    cudaFuncSetAttribute(hgemm<128, F_BIAS | F_OUTH, 0>,
                         cudaFuncAttributeMaxDynamicSharedMemorySize, SMEM_NN128);
    cudaFuncSetAttribute(hgemm<128, F_SCALE | F_OUTF, 1>,
                         cudaFuncAttributeMaxDynamicSharedMemorySize, SMEM_BT128);
    cudaFuncSetAttribute(hgemm<64, F_OUTH, 0>,
                         cudaFuncAttributeMaxDynamicSharedMemorySize, SMEM_NN64);
    cudaFuncSetAttribute(hgemm<128, F_BIAS | F_RES | F_OUTF, 0>,
                         cudaFuncAttributeMaxDynamicSharedMemorySize, SMEM_NN128);
    cudaFuncSetAttribute(hgemm<128, F_BIAS | F_GELU | F_OUTH, 0>,
                         cudaFuncAttributeMaxDynamicSharedMemorySize, SMEM_NN128);
    cudaFuncSetAttribute(hgemm<128, F_BIAS | F_RES | F_OUTF | F_FUSE, 0>,
                         cudaFuncAttributeMaxDynamicSharedMemorySize, SMEM_NN128);

    const int n0 = DIMC * 3 * DIMC / 4;
    const int n1 = DIMC * DIMC / 4;
    const int n2 = DIMC * MLPC / 4;
    const int n3 = MLPC * (DIMC - PART) / 4;
    const int n4 = 8 * MLPC * PART / 4;
    const int ntot = n0 + n1 + n2 + n3 + n4;
    cvt5_k<<<(ntot + 255) / 256, 256>>>(qkv_w, qkvw_h, n0,
                                        out_w, outw_h, n1,
                                        fc1_w, fc1w_h, n2,
                                        fc2_w, fc2w_h, n3,
                                        exp_w, expw_h, n4);

    layernorm_h_k<<<TOK, 256>>>(x, ln1_w, ln1_b, xn_h);

    hgemm<128, F_BIAS | F_OUTH, 0><<<dim3(24, 32, 1), 256, SMEM_NN128>>>(
        xn_h, DIMC, qkvw_h, 3 * DIMC, nullptr, qkv_h, 3 * DIMC, DIMC,
        qkv_b, nullptr, 0, 0.f, nullptr, 0, 0, nullptr, 0, nullptr,
        0L, 0L, 0L, 0L, 0L, 0L);

    hgemm<128, F_SCALE | F_OUTF, 1><<<dim3(4, 4, 128), 256, SMEM_BT128>>>(
        qkv_h, 3 * DIMC, qkv_h + DIMC, 3 * DIMC, attn, nullptr, NSEQ, HD,
        nullptr, nullptr, 0, 0.03125f, nullptr, 0, 0, nullptr, 0, nullptr,
        (long)NSEQ * 3 * DIMC, (long)HD,
        (long)NSEQ * 3 * DIMC, (long)HD,
        16L * NSEQ * NSEQ, (long)NSEQ * NSEQ);

    softmax_k<<<128 * NSEQ, 128>>>(attn, attn_h);

    hgemm<64, F_OUTH, 0><<<dim3(1, 4, 128), 256, SMEM_NN64>>>(
        attn_h, NSEQ, qkv_h + 2 * DIMC, 3 * DIMC, nullptr, ctx_h, DIMC, NSEQ,
        nullptr, nullptr, 0, 0.f, nullptr, 0, 0, nullptr, 0, nullptr,
        16L * NSEQ * NSEQ, (long)NSEQ * NSEQ,
        (long)NSEQ * 3 * DIMC, (long)HD,
        (long)NSEQ * DIMC, (long)HD);

    hgemm<128, F_BIAS | F_RES | F_OUTF, 0><<<dim3(8, 32, 1), 256, SMEM_NN128>>>(
        ctx_h, DIMC, outw_h, DIMC, x1, nullptr, DIMC, DIMC,
        out_b, x, DIMC, 0.f, nullptr, 0, 0, nullptr, 0, nullptr,
        0L, 0L, 0L, 0L, 0L, 0L);

    layernorm_h_k<<<TOK, 256>>>(x1, ln2_w, ln2_b, xn_h);

    hgemm<128, F_BIAS | F_GELU | F_OUTH, 0><<<dim3(32, 32, 1), 256, SMEM_NN128>>>(
        xn_h, DIMC, fc1w_h, MLPC, nullptr, h_h, MLPC, DIMC,
        fc1_b, nullptr, 0, 0.f, nullptr, 0, 0, nullptr, 0, nullptr,
        0L, 0L, 0L, 0L, 0L, 0L);

    /* fused fc2 (cols 0..767) + per-batch expert (cols 768..1023), one wave */
    hgemm<128, F_BIAS | F_RES | F_OUTF | F_FUSE, 0><<<dim3(8, 32, 1), 256, SMEM_NN128>>>(
        h_h, MLPC, fc2w_h, DIMC - PART, out_final, nullptr, DIMC, MLPC,
        fc2_b, x1, DIMC, 0.f,
        indices, (long)MLPC * PART, PART,
        expw_h, PART, exp_b,
        0L, 0L, 0L, 0L, 0L, 0L);
}

// round 9
// speedup vs baseline: 1.2768x; 1.0327x over previous
#include <cuda_runtime.h>
#include <cuda_fp16.h>
#include <cuda_pipeline.h>
#include <mma.h>
#include <math.h>

#define TOK   4096
#define DIMC  1024
#define MLPC  4096
#define NSEQ  512
#define HD    64
#define PART  256

#define F_BIAS  1
#define F_GELU  2
#define F_RES   4
#define F_SCALE 8
#define F_OUTF  16
#define F_OUTH  32
#define F_FUSE  64

using namespace nvcuda;

/* static device scratch */
__device__ __half g_xn_h [TOK * DIMC];
__device__ __half g_qkv_h[TOK * 3 * DIMC];
__device__ __half g_ctx_h[TOK * DIMC];
__device__ float  g_x1   [TOK * DIMC];
__device__ __half g_h_h  [TOK * MLPC];
__device__ __half g_qkvw_h[DIMC * 3 * DIMC];
__device__ __half g_outw_h[DIMC * DIMC];
__device__ __half g_fc1w_h[DIMC * MLPC];
__device__ __half g_fc2w_h[MLPC * (DIMC - PART)];
__device__ __half g_expw_h[8 * MLPC * PART];

__device__ __forceinline__ float gelu_f(float v) {
    return 0.5f * v * (1.0f + erff(v * 0.70710678118654752f));
}

/* fused fp32 to fp16 conversion over five weight tensors */
__global__ void cvt5_k(const float* __restrict__ w0, __half* __restrict__ o0, int n0,
                       const float* __restrict__ w1, __half* __restrict__ o1, int n1,
                       const float* __restrict__ w2, __half* __restrict__ o2, int n2,
                       const float* __restrict__ w3, __half* __restrict__ o3, int n3,
                       const float* __restrict__ w4, __half* __restrict__ o4, int n4) {
    int i = blockIdx.x * blockDim.x + threadIdx.x;
    const float* in;
    __half* out;
    if (i < n0) {
        in = w0; out = o0;
    } else if (i < n0 + n1) {
        i -= n0; in = w1; out = o1;
    } else if (i < n0 + n1 + n2) {
        i -= n0 + n1; in = w2; out = o2;
    } else if (i < n0 + n1 + n2 + n3) {
        i -= n0 + n1 + n2; in = w3; out = o3;
    } else if (i < n0 + n1 + n2 + n3 + n4) {
        i -= n0 + n1 + n2 + n3; in = w4; out = o4;
    } else {
        return;
    }
    float4 v = reinterpret_cast<const float4*>(in)[i];
    reinterpret_cast<__half2*>(out)[i * 2 + 0] = __floats2half2_rn(v.x, v.y);
    reinterpret_cast<__half2*>(out)[i * 2 + 1] = __floats2half2_rn(v.z, v.w);
}

/* layernorm fp32 in, fp16 out */
__global__ void layernorm_h_k(const float* __restrict__ x,
                              const float* __restrict__ w,
                              const float* __restrict__ b,
                              __half* __restrict__ out) {
    int row = blockIdx.x;
    int t = threadIdx.x;
    float4 v = reinterpret_cast<const float4*>(x + (size_t)row * DIMC)[t];
    float s  = v.x + v.y + v.z + v.w;
    float sq = v.x * v.x + v.y * v.y + v.z * v.z + v.w * v.w;
    #pragma unroll
    for (int o = 16; o > 0; o >>= 1) {
        s  += __shfl_down_sync(0xffffffffu, s,  o);
        sq += __shfl_down_sync(0xffffffffu, sq, o);
    }
    __shared__ float ss[8];
    __shared__ float sq2[8];
    __shared__ float mean_s;
    __shared__ float rstd_s;
    int lane = t & 31;
    int wp = t >> 5;
    if (lane == 0) { ss[wp] = s; sq2[wp] = sq; }
    __syncthreads();
    if (t == 0) {
        float S = 0.f;
        float Q = 0.f;
        #pragma unroll
        for (int i = 0; i < 8; i++) { S += ss[i]; Q += sq2[i]; }
        float m = S * (1.0f / DIMC);
        mean_s = m;
        rstd_s = rsqrtf(Q * (1.0f / DIMC) - m * m + 1e-5f);
    }
    __syncthreads();
    float m = mean_s;
    float r = rstd_s;
    float4 wv = reinterpret_cast<const float4*>(w)[t];
    float4 bv = reinterpret_cast<const float4*>(b)[t];
    float o0 = (v.x - m) * r * wv.x + bv.x;
    float o1 = (v.y - m) * r * wv.y + bv.y;
    float o2 = (v.z - m) * r * wv.z + bv.z;
    float o3 = (v.w - m) * r * wv.w + bv.w;
    __half2* op = reinterpret_cast<__half2*>(out + (size_t)row * DIMC);
    op[t * 2 + 0] = __floats2half2_rn(o0, o1);
    op[t * 2 + 1] = __floats2half2_rn(o2, o3);
}

/*
 * Fused attention: per CTA = one (b,h) and a block of 32 query rows.
 * S = scale * Q K^T computed by WMMA into smem; in-CTA softmax writes the
 * fp32 attn output and fp16 P into smem; V (prefetched over the K smem
 * region during softmax) then P @ V with per-warp k-slices and an smem
 * reduction into ctx (fp16).
 */
__global__ __launch_bounds__(256, 1)
void attn_fused_k(const __half* __restrict__ qkv,
                  float* __restrict__ attn,
                  __half* __restrict__ ctx) {
    const int rb = blockIdx.x;
    const int bh = blockIdx.y;
    const int b = bh >> 4;
    const int h = bh & 15;
    const int tid = threadIdx.x;
    const int warp = tid >> 5;
    const int lane = tid & 31;

    extern __shared__ __align__(16) char dyn[];
    __half* Ks = reinterpret_cast<__half*>(dyn);              /* 512 x 72 halves, later V */
    __half* Qs = Ks + 512 * 72;                               /* 32 x 72 halves */
    float*  Ss = reinterpret_cast<float*>(Qs + 32 * 72);      /* 32 x 520 floats */
    __half* Ps = reinterpret_cast<__half*>(Ss + 32 * 520);    /* 32 x 528 halves */

    const __half* Qg = qkv + (long)b * NSEQ * 3 * DIMC + (long)(rb * 32) * 3 * DIMC + h * HD;
    const __half* Kg = qkv + (long)b * NSEQ * 3 * DIMC + DIMC + h * HD;
    const __half* Vg = Kg + DIMC;

    /* async load Q strip and full K */
    {
        const int row = tid >> 3;
        const int c = tid & 7;
        __pipeline_memcpy_async(&Qs[row * 72 + c * 8], Qg + (long)row * 3072 + c * 8, 16);
    }
    #pragma unroll
    for (int q = 0; q < 16; q++) {
        const int idx = q * 256 + tid;
        const int row = idx >> 3;
        const int c = idx & 7;
        __pipeline_memcpy_async(&Ks[row * 72 + c * 8], Kg + (long)row * 3072 + c * 8, 16);
    }
    __pipeline_commit();
    __pipeline_wait_prior(0);
    __syncthreads();

    /* S = Q K^T: warp w computes rows 0..31, cols [64w, 64w+64) */
    {
        wmma::fragment<wmma::accumulator, 16, 16, 16, float> sacc[2][4];
        #pragma unroll
        for (int mt = 0; mt < 2; mt++) {
            #pragma unroll
            for (int nt = 0; nt < 4; nt++) wmma::fill_fragment(sacc[mt][nt], 0.0f);
        }
        #pragma unroll
        for (int ks = 0; ks < 64; ks += 16) {
            wmma::fragment<wmma::matrix_a, 16, 16, 16, __half, wmma::row_major> af[2];
            #pragma unroll
            for (int mt = 0; mt < 2; mt++) {
                wmma::load_matrix_sync(af[mt], &Qs[(mt * 16) * 72 + ks], 72);
            }
            wmma::fragment<wmma::matrix_b, 16, 16, 16, __half, wmma::col_major> bf[4];
            #pragma unroll
            for (int nt = 0; nt < 4; nt++) {
                wmma::load_matrix_sync(bf[nt], &Ks[(warp * 64 + nt * 16) * 72 + ks], 72);
            }
            #pragma unroll
            for (int mt = 0; mt < 2; mt++) {
                #pragma unroll
                for (int nt = 0; nt < 4; nt++) {
                    wmma::mma_sync(sacc[mt][nt], af[mt], bf[nt], sacc[mt][nt]);
                }
            }
        }
        #pragma unroll
        for (int mt = 0; mt < 2; mt++) {
            #pragma unroll
            for (int nt = 0; nt < 4; nt++) {
                wmma::store_matrix_sync(&Ss[(mt * 16) * 520 + warp * 64 + nt * 16],
                                        sacc[mt][nt], 520, wmma::mem_row_major);
            }
        }
    }
    __syncthreads();

    /* prefetch V over the K region while softmax runs */
    #pragma unroll
    for (int q = 0; q < 16; q++) {
        const int idx = q * 256 + tid;
        const int row = idx >> 3;
        const int c = idx & 7;
        __pipeline_memcpy_async(&Ks[row * 72 + c * 8], Vg + (long)row * 3072 + c * 8, 16);
    }
    __pipeline_commit();

    /* softmax: warp w handles rows 4w..4w+3; write attn fp32 + P half */
    {
        float* attn_base = attn + ((long)bh * NSEQ + (long)rb * 32) * NSEQ;
        #pragma unroll
        for (int rr = 0; rr < 4; rr++) {
            const int row = warp * 4 + rr;
            float v[16];
            float mx = -1e30f;
            #pragma unroll
            for (int j = 0; j < 16; j++) {
                v[j] = Ss[row * 520 + lane + 32 * j] * 0.03125f;
                mx = fmaxf(mx, v[j]);
            }
            #pragma unroll
            for (int o = 16; o > 0; o >>= 1) mx = fmaxf(mx, __shfl_xor_sync(0xffffffffu, mx, o));
            float sum = 0.f;
            #pragma unroll
            for (int j = 0; j < 16; j++) {
                v[j] = expf(v[j] - mx);
                sum += v[j];
            }
            #pragma unroll
            for (int o = 16; o > 0; o >>= 1) sum += __shfl_xor_sync(0xffffffffu, sum, o);
            const float inv = 1.0f / sum;
            #pragma unroll
            for (int j = 0; j < 16; j++) {
                const float e = v[j] * inv;
                attn_base[(long)row * NSEQ + lane + 32 * j] = e;
                Ps[row * 528 + lane + 32 * j] = __float2half(e);
            }
        }
    }
    __pipeline_wait_prior(0);
    __syncthreads();

    /* P @ V: warp w handles k-slice [64w, 64w+64), partial 32x64 into Ss */
    {
        wmma::fragment<wmma::accumulator, 16, 16, 16, float> oacc[2][4];
        #pragma unroll
        for (int mt = 0; mt < 2; mt++) {
            #pragma unroll
            for (int nt = 0; nt < 4; nt++) wmma::fill_fragment(oacc[mt][nt], 0.0f);
        }
        #pragma unroll
        for (int ks = 0; ks < 64; ks += 16) {
            const int kg = warp * 64 + ks;
            wmma::fragment<wmma::matrix_a, 16, 16, 16, __half, wmma::row_major> af[2];
            #pragma unroll
            for (int mt = 0; mt < 2; mt++) {
                wmma::load_matrix_sync(af[mt], &Ps[(mt * 16) * 528 + kg], 528);
            }
            wmma::fragment<wmma::matrix_b, 16, 16, 16, __half, wmma::row_major> bf[4];
            #pragma unroll
            for (int nt = 0; nt < 4; nt++) {
                wmma::load_matrix_sync(bf[nt], &Ks[kg * 72 + nt * 16], 72);
            }
            #pragma unroll
            for (int mt = 0; mt < 2; mt++) {
                #pragma unroll
                for (int nt = 0; nt < 4; nt++) {
                    wmma::mma_sync(oacc[mt][nt], af[mt], bf[nt], oacc[mt][nt]);
                }
            }
        }
        __syncthreads();
        #pragma unroll
        for (int mt = 0; mt < 2; mt++) {
            #pragma unroll
            for (int nt = 0; nt < 4; nt++) {
                wmma::store_matrix_sync(&Ss[warp * 2048 + (mt * 16) * 64 + nt * 16],
                                        oacc[mt][nt], 64, wmma::mem_row_major);
            }
        }
    }
    __syncthreads();

    /* reduce 8 warp partials and write ctx (fp16) */
    {
        const int r = tid >> 3;
        const int c0 = (tid & 7) * 8;
        float a8[8];
        #pragma unroll
        for (int j = 0; j < 8; j++) a8[j] = 0.f;
        #pragma unroll
        for (int w = 0; w < 8; w++) {
            #pragma unroll
            for (int j = 0; j < 8; j++) a8[j] += Ss[w * 2048 + r * 64 + c0 + j];
        }
        __half2 hv[4];
        #pragma unroll
        for (int j = 0; j < 4; j++) hv[j] = __floats2half2_rn(a8[2 * j], a8[2 * j + 1]);
        __half* cp = ctx + (long)b * NSEQ * DIMC + (long)(rb * 32 + r) * DIMC + h * 64 + c0;
        *reinterpret_cast<float4*>(cp) = *reinterpret_cast<float4*>(hv);
    }
}

/* one pipeline stage load: A tile 128x32, B tile 32xBN.
   Bp is pre-offset to the block's column start. */
template<int BN>
__device__ __forceinline__ void load_stage(const __half* A, int lda,
                                           const __half* Bp, long ldbv,
                                           int brow, int k0,
                                           __half* As, __half* Bs, int tid) {
    const int AP  = 40;
    const int BPN = BN + 8;
    const int lr = tid >> 1;
    const int lc = (tid & 1) * 16;
    const __half* ga = A + (long)(brow + lr) * lda + k0 + lc;
    __pipeline_memcpy_async(&As[lr * AP + lc], ga, 16);
    __pipeline_memcpy_async(&As[lr * AP + lc + 8], ga + 8, 16);
    const int CH = BN / 8;
    #pragma unroll
    for (int q = 0; q < (32 * CH + 255) / 256; q++) {
        const int idx = tid + q * 256;
        if (idx < 32 * CH) {
            const int r = idx / CH;
            const int c = idx % CH;
            __pipeline_memcpy_async(&Bs[r * BPN + c * 8],
                                    Bp + (long)(k0 + r) * ldbv + c * 8, 16);
        }
    }
}

/*
 * WMMA tensor-core GEMM (NN). Block tile 128 x BN, K-step 32, 3-stage
 * cp.async pipeline. 8 warps as 4(m) x 2(n). F_FUSE: column blocks at or
 * beyond DIMC-PART read the per-batch expert weight B2/bias2 instead.
 */
template<int BN, int FLAGS>
__global__ __launch_bounds__(256, 2)
void hgemm(const __half* __restrict__ A, int lda,
           const __half* __restrict__ B, int ldb,
           float* __restrict__ Cf, __half* __restrict__ Ch, int ldc,
           int K,
           const float* __restrict__ bias,
           const float* __restrict__ res, int ldr,
           const int* __restrict__ indices, long wstride, int bstride,
           const __half* __restrict__ B2, int ldb2,
           const float* __restrict__ bias2)
{
    const int brow = blockIdx.y * 128;
    const int bcol = blockIdx.x * BN;

    const __half* Bp = B + bcol;
    const float* biasp = (FLAGS & F_BIAS) ? (bias + bcol) : bias;
    long ldbv = ldb;
    if ((FLAGS & F_FUSE) && bcol >= (DIMC - PART)) {
        const int idx = indices[brow >> 9];
        Bp    = B2 + (long)idx * wstride + (bcol - (DIMC - PART));
        biasp = bias2 + (long)idx * bstride + (bcol - (DIMC - PART));
        ldbv  = ldb2;
    }

    constexpr int AP  = 40;
    constexpr int BPN = BN + 8;
    constexpr int ASZ = 128 * AP;
    constexpr int BSZ = 32 * BPN;

    extern __shared__ __align__(16) char dyn[];
    __half* As = reinterpret_cast<__half*>(dyn);
    __half* Bs = As + 3 * ASZ;

    const int tid  = threadIdx.x;
    const int warp = tid >> 5;
    const int lane = tid & 31;
    const int wm = warp & 3;
    const int wn = warp >> 2;
    constexpr int NTF = BN / 32;

    wmma::fragment<wmma::accumulator, 16, 16, 16, float> acc[2][NTF];
    #pragma unroll
    for (int i = 0; i < 2; i++) {
        #pragma unroll
        for (int j = 0; j < NTF; j++) wmma::fill_fragment(acc[i][j], 0.0f);
    }

    const int iters = K >> 5;

    load_stage<BN>(A, lda, Bp, ldbv, brow, 0, As, Bs, tid);
    __pipeline_commit();
    if (iters > 1) {
        load_stage<BN>(A, lda, Bp, ldbv, brow, 32, As + ASZ, Bs + BSZ, tid);
        __pipeline_commit();
    }

    for (int it = 0; it < iters; ++it) {
        if (it + 1 < iters) {
            __pipeline_wait_prior(1);
        } else {
            __pipeline_wait_prior(0);
        }
        __syncthreads();
        if (it + 2 < iters) {
            const int ns = (it + 2) % 3;
            load_stage<BN>(A, lda, Bp, ldbv, brow, (it + 2) * 32,
                           As + ns * ASZ, Bs + ns * BSZ, tid);
            __pipeline_commit();
        }
        const int slot = it % 3;

        #pragma unroll
        for (int ks = 0; ks < 32; ks += 16) {
            wmma::fragment<wmma::matrix_a, 16, 16, 16, __half, wmma::row_major> af[2];
            #pragma unroll
            for (int mt = 0; mt < 2; mt++) {
                const __half* ap = &As[slot * ASZ + (wm * 32 + mt * 16) * AP + ks];
                wmma::load_matrix_sync(af[mt], ap, AP);
            }
            wmma::fragment<wmma::matrix_b, 16, 16, 16, __half, wmma::row_major> bf[NTF];
            #pragma unroll
            for (int nt = 0; nt < NTF; nt++) {
                const __half* bp = &Bs[slot * BSZ + ks * BPN + wn * (BN / 2) + nt * 16];
                wmma::load_matrix_sync(bf[nt], bp, BPN);
            }
            #pragma unroll
            for (int mt = 0; mt < 2; mt++) {
                #pragma unroll
                for (int nt = 0; nt < NTF; nt++) {
                    wmma::mma_sync(acc[mt][nt], af[mt], bf[nt], acc[mt][nt]);
                }
            }
        }
    }

    __syncthreads();

    /* epilogue: stage each 16x16 accumulator through smem */
    float* stage = reinterpret_cast<float*>(dyn) + warp * 16 * 20;
    const int er = lane >> 1;
    const int ec = (lane & 1) * 8;
    #pragma unroll
    for (int mt = 0; mt < 2; mt++) {
        #pragma unroll
        for (int nt = 0; nt < NTF; nt++) {
            wmma::store_matrix_sync(stage, acc[mt][nt], 20, wmma::mem_row_major);
            __syncwarp();
            const int row = brow + wm * 32 + mt * 16 + er;
            const int lcol = wn * (BN / 2) + nt * 16 + ec;
            const int col = bcol + lcol;
            float v[8];
            #pragma unroll
            for (int j = 0; j < 8; j++) v[j] = stage[er * 20 + ec + j];
            if (FLAGS & F_BIAS) {
                #pragma unroll
                for (int j = 0; j < 8; j++) v[j] += biasp[lcol + j];
            }
            if (FLAGS & F_GELU) {
                #pragma unroll
                for (int j = 0; j < 8; j++) v[j] = gelu_f(v[j]);
            }
            if (FLAGS & F_RES) {
                #pragma unroll
                for (int j = 0; j < 8; j++) v[j] += res[(long)row * ldr + col + j];
            }
            const long off = (long)row * ldc + col;
            if (FLAGS & F_OUTF) {
                float4 f0;
                f0.x = v[0]; f0.y = v[1]; f0.z = v[2]; f0.w = v[3];
                float4 f1;
                f1.x = v[4]; f1.y = v[5]; f1.z = v[6]; f1.w = v[7];
                *reinterpret_cast<float4*>(&Cf[off]) = f0;
                *reinterpret_cast<float4*>(&Cf[off + 4]) = f1;
            }
            if (FLAGS & F_OUTH) {
                __half2* hp = reinterpret_cast<__half2*>(&Ch[off]);
                hp[0] = __floats2half2_rn(v[0], v[1]);
                hp[1] = __floats2half2_rn(v[2], v[3]);
                hp[2] = __floats2half2_rn(v[4], v[5]);
                hp[3] = __floats2half2_rn(v[6], v[7]);
            }
            __syncwarp();
        }
    }
}

#define SMEM_NN128 (3 * (128 * 40 + 32 * 136) * 2)
#define SMEM_ATTN  178688

extern "C" void kernel_launch(void* const* d_in, const int* in_sizes, int n_in,
                              void* d_out, int out_size) {
    const float* x       = (const float*)d_in[0];
    const int*   indices = (const int*)  d_in[1];
    const float* ln1_w   = (const float*)d_in[2];
    const float* ln1_b   = (const float*)d_in[3];
    const float* qkv_w   = (const float*)d_in[4];
    const float* qkv_b   = (const float*)d_in[5];
    const float* out_w   = (const float*)d_in[6];
    const float* out_b   = (const float*)d_in[7];
    const float* ln2_w   = (const float*)d_in[8];
    const float* ln2_b   = (const float*)d_in[9];
    const float* fc1_w   = (const float*)d_in[10];
    const float* fc1_b   = (const float*)d_in[11];
    const float* fc2_w   = (const float*)d_in[12];
    const float* fc2_b   = (const float*)d_in[13];
    const float* exp_w   = (const float*)d_in[14];
    const float* exp_b   = (const float*)d_in[15];

    float* out_final = (float*)d_out;
    float* attn      = out_final + (size_t)TOK * DIMC;

    void* p;
    cudaGetSymbolAddress(&p, g_xn_h);
    __half* xn_h = (__half*)p;
    cudaGetSymbolAddress(&p, g_qkv_h);
    __half* qkv_h = (__half*)p;
    cudaGetSymbolAddress(&p, g_ctx_h);
    __half* ctx_h = (__half*)p;
    cudaGetSymbolAddress(&p, g_x1);
    float* x1 = (float*)p;
    cudaGetSymbolAddress(&p, g_h_h);
    __half* h_h = (__half*)p;
    cudaGetSymbolAddress(&p, g_qkvw_h);
    __half* qkvw_h = (__half*)p;
    cudaGetSymbolAddress(&p, g_outw_h);
    __half* outw_h = (__half*)p;
    cudaGetSymbolAddress(&p, g_fc1w_h);
    __half* fc1w_h = (__half*)p;
    cudaGetSymbolAddress(&p, g_fc2w_h);
    __half* fc2w_h = (__half*)p;
    cudaGetSymbolAddress(&p, g_expw_h);
    __half* expw_h = (__half*)p;

    cudaFuncSetAttribute(hgemm<128, F_BIAS | F_OUTH>,
                         cudaFuncAttributeMaxDynamicSharedMemorySize, SMEM_NN128);
    cudaFuncSetAttribute(hgemm<128, F_BIAS | F_RES | F_OUTF>,
                         cudaFuncAttributeMaxDynamicSharedMemorySize, SMEM_NN128);
    cudaFuncSetAttribute(hgemm<128, F_BIAS | F_GELU | F_OUTH>,
                         cudaFuncAttributeMaxDynamicSharedMemorySize, SMEM_NN128);
    cudaFuncSetAttribute(hgemm<128, F_BIAS | F_RES | F_OUTF | F_FUSE>,
                         cudaFuncAttributeMaxDynamicSharedMemorySize, SMEM_NN128);
    cudaFuncSetAttribute(attn_fused_k,
                         cudaFuncAttributeMaxDynamicSharedMemorySize, SMEM_ATTN);

    const int n0 = DIMC * 3 * DIMC / 4;
    const int n1 = DIMC * DIMC / 4;
    const int n2 = DIMC * MLPC / 4;
    const int n3 = MLPC * (DIMC - PART) / 4;
    const int n4 = 8 * MLPC * PART / 4;
    const int ntot = n0 + n1 + n2 + n3 + n4;
    cvt5_k<<<(ntot + 255) / 256, 256>>>(qkv_w, qkvw_h, n0,
                                        out_w, outw_h, n1,
                                        fc1_w, fc1w_h, n2,
                                        fc2_w, fc2w_h, n3,
                                        exp_w, expw_h, n4);

    layernorm_h_k<<<TOK, 256>>>(x, ln1_w, ln1_b, xn_h);

    hgemm<128, F_BIAS | F_OUTH><<<dim3(24, 32), 256, SMEM_NN128>>>(
        xn_h, DIMC, qkvw_h, 3 * DIMC, nullptr, qkv_h, 3 * DIMC, DIMC,
        qkv_b, nullptr, 0, nullptr, 0, 0, nullptr, 0, nullptr);

    attn_fused_k<<<dim3(16, 128), 256, SMEM_ATTN>>>(qkv_h, attn, ctx_h);

    hgemm<128, F_BIAS | F_RES | F_OUTF><<<dim3(8, 32), 256, SMEM_NN128>>>(
        ctx_h, DIMC, outw_h, DIMC, x1, nullptr, DIMC, DIMC,
        out_b, x, DIMC, nullptr, 0, 0, nullptr, 0, nullptr);

    layernorm_h_k<<<TOK, 256>>>(x1, ln2_w, ln2_b, xn_h);

    hgemm<128, F_BIAS | F_GELU | F_OUTH><<<dim3(32, 32), 256, SMEM_NN128>>>(
        xn_h, DIMC, fc1w_h, MLPC, nullptr, h_h, MLPC, DIMC,
        fc1_b, nullptr, 0, nullptr, 0, 0, nullptr, 0, nullptr);

    hgemm<128, F_BIAS | F_RES | F_OUTF | F_FUSE><<<dim3(8, 32), 256, SMEM_NN128>>>(
        h_h, MLPC, fc2w_h, DIMC - PART, out_final, nullptr, DIMC, MLPC,
        fc2_b, x1, DIMC,
        indices, (long)MLPC * PART, PART,
        expw_h, PART, exp_b);
}

// round 10
// speedup vs baseline: 1.3386x; 1.0484x over previous
#include <cuda_runtime.h>
#include <cuda_fp16.h>
#include <cuda_pipeline.h>
#include <mma.h>
#include <math.h>

#define TOK   4096
#define DIMC  1024
#define MLPC  4096
#define NSEQ  512
#define HD    64
#define PART  256

#define F_BIAS  1
#define F_GELU  2
#define F_RES   4
#define F_OUTF  16
#define F_OUTH  32
#define F_FUSE  64

using namespace nvcuda;

/* static device scratch */
__device__ __half g_xn_h [TOK * DIMC];
__device__ __half g_qkv_h[TOK * 3 * DIMC];
__device__ __half g_ctx_h[TOK * DIMC];
__device__ float  g_x1   [TOK * DIMC];
__device__ __half g_h_h  [TOK * MLPC];
__device__ __half g_qkvw_h[DIMC * 3 * DIMC];
__device__ __half g_outw_h[DIMC * DIMC];
__device__ __half g_fc1w_h[DIMC * MLPC];
__device__ __half g_fc2w_h[MLPC * (DIMC - PART)];
__device__ __half g_expw_h[8 * MLPC * PART];

__device__ __forceinline__ float gelu_f(float v) {
    return 0.5f * v * (1.0f + erff(v * 0.70710678118654752f));
}

/* fused fp32 to fp16 conversion over five weight tensors */
__global__ void cvt5_k(const float* __restrict__ w0, __half* __restrict__ o0, int n0,
                       const float* __restrict__ w1, __half* __restrict__ o1, int n1,
                       const float* __restrict__ w2, __half* __restrict__ o2, int n2,
                       const float* __restrict__ w3, __half* __restrict__ o3, int n3,
                       const float* __restrict__ w4, __half* __restrict__ o4, int n4) {
    int i = blockIdx.x * blockDim.x + threadIdx.x;
    const float* in;
    __half* out;
    if (i < n0) {
        in = w0; out = o0;
    } else if (i < n0 + n1) {
        i -= n0; in = w1; out = o1;
    } else if (i < n0 + n1 + n2) {
        i -= n0 + n1; in = w2; out = o2;
    } else if (i < n0 + n1 + n2 + n3) {
        i -= n0 + n1 + n2; in = w3; out = o3;
    } else if (i < n0 + n1 + n2 + n3 + n4) {
        i -= n0 + n1 + n2 + n3; in = w4; out = o4;
    } else {
        return;
    }
    float4 v = reinterpret_cast<const float4*>(in)[i];
    reinterpret_cast<__half2*>(out)[i * 2 + 0] = __floats2half2_rn(v.x, v.y);
    reinterpret_cast<__half2*>(out)[i * 2 + 1] = __floats2half2_rn(v.z, v.w);
}

/* layernorm fp32 in, fp16 out */
__global__ void layernorm_h_k(const float* __restrict__ x,
                              const float* __restrict__ w,
                              const float* __restrict__ b,
                              __half* __restrict__ out) {
    int row = blockIdx.x;
    int t = threadIdx.x;
    float4 v = reinterpret_cast<const float4*>(x + (size_t)row * DIMC)[t];
    float s  = v.x + v.y + v.z + v.w;
    float sq = v.x * v.x + v.y * v.y + v.z * v.z + v.w * v.w;
    #pragma unroll
    for (int o = 16; o > 0; o >>= 1) {
        s  += __shfl_down_sync(0xffffffffu, s,  o);
        sq += __shfl_down_sync(0xffffffffu, sq, o);
    }
    __shared__ float ss[8];
    __shared__ float sq2[8];
    __shared__ float mean_s;
    __shared__ float rstd_s;
    int lane = t & 31;
    int wp = t >> 5;
    if (lane == 0) { ss[wp] = s; sq2[wp] = sq; }
    __syncthreads();
    if (t == 0) {
        float S = 0.f;
        float Q = 0.f;
        #pragma unroll
        for (int i = 0; i < 8; i++) { S += ss[i]; Q += sq2[i]; }
        float m = S * (1.0f / DIMC);
        mean_s = m;
        rstd_s = rsqrtf(Q * (1.0f / DIMC) - m * m + 1e-5f);
    }
    __syncthreads();
    float m = mean_s;
    float r = rstd_s;
    float4 wv = reinterpret_cast<const float4*>(w)[t];
    float4 bv = reinterpret_cast<const float4*>(b)[t];
    float o0 = (v.x - m) * r * wv.x + bv.x;
    float o1 = (v.y - m) * r * wv.y + bv.y;
    float o2 = (v.z - m) * r * wv.z + bv.z;
    float o3 = (v.w - m) * r * wv.w + bv.w;
    __half2* op = reinterpret_cast<__half2*>(out + (size_t)row * DIMC);
    op[t * 2 + 0] = __floats2half2_rn(o0, o1);
    op[t * 2 + 1] = __floats2half2_rn(o2, o3);
}

/*
 * Persistent fused attention: one CTA per (b,h). K and V live in smem for
 * the whole kernel; loop over 16 chunks of 32 query rows with
 * double-buffered Q prefetch. Per chunk: S = Q K^T (8 warps, 64-col
 * slices) -> softmax (writes fp32 attn + fp16 P aliased over S rows) ->
 * P @ V (2m x 4n warps, full K depth, no reduction) -> ctx fp16.
 */
__global__ __launch_bounds__(256, 1)
void attn_fused_k(const __half* __restrict__ qkv,
                  float* __restrict__ attn,
                  __half* __restrict__ ctx) {
    const int bh = blockIdx.x;
    const int b = bh >> 4;
    const int h = bh & 15;
    const int tid = threadIdx.x;
    const int warp = tid >> 5;
    const int lane = tid & 31;

    extern __shared__ __align__(16) char dyn[];
    __half* Ks = reinterpret_cast<__half*>(dyn);            /* 512 x 72 halves */
    __half* Vs = Ks + 512 * 72;                             /* 512 x 72 halves */
    float*  Ss = reinterpret_cast<float*>(Vs + 512 * 72);   /* 32 x 520 floats */
    __half* Qs = reinterpret_cast<__half*>(Ss + 32 * 520);  /* 2 x 32 x 72 halves */

    const __half* Qg = qkv + (long)b * NSEQ * 3 * DIMC + h * HD;
    const __half* Kg = Qg + DIMC;
    const __half* Vg = Qg + 2 * DIMC;

    /* load all of K, V and Q chunk 0 */
    #pragma unroll
    for (int q = 0; q < 16; q++) {
        const int idx = q * 256 + tid;
        const int row = idx >> 3;
        const int c = idx & 7;
        __pipeline_memcpy_async(&Ks[row * 72 + c * 8], Kg + (long)row * 3072 + c * 8, 16);
        __pipeline_memcpy_async(&Vs[row * 72 + c * 8], Vg + (long)row * 3072 + c * 8, 16);
    }
    {
        const int row = tid >> 3;
        const int c = tid & 7;
        __pipeline_memcpy_async(&Qs[row * 72 + c * 8], Qg + (long)row * 3072 + c * 8, 16);
    }
    __pipeline_commit();
    __pipeline_wait_prior(0);
    __syncthreads();

    for (int chunk = 0; chunk < 16; chunk++) {
        const int cur = chunk & 1;
        __half* Qc = Qs + cur * 32 * 72;

        /* prefetch next Q chunk into the other buffer */
        if (chunk + 1 < 16) {
            const int row = tid >> 3;
            const int c = tid & 7;
            __pipeline_memcpy_async(&Qs[(1 - cur) * 32 * 72 + row * 72 + c * 8],
                                    Qg + (long)((chunk + 1) * 32 + row) * 3072 + c * 8, 16);
            __pipeline_commit();
        }

        /* S = Q K^T : warp w covers cols [64w, 64w+64) */
        {
            wmma::fragment<wmma::accumulator, 16, 16, 16, float> sacc[2][4];
            #pragma unroll
            for (int mt = 0; mt < 2; mt++) {
                #pragma unroll
                for (int nt = 0; nt < 4; nt++) wmma::fill_fragment(sacc[mt][nt], 0.0f);
            }
            #pragma unroll
            for (int ks = 0; ks < 64; ks += 16) {
                wmma::fragment<wmma::matrix_a, 16, 16, 16, __half, wmma::row_major> af[2];
                #pragma unroll
                for (int mt = 0; mt < 2; mt++) {
                    wmma::load_matrix_sync(af[mt], &Qc[(mt * 16) * 72 + ks], 72);
                }
                wmma::fragment<wmma::matrix_b, 16, 16, 16, __half, wmma::col_major> bf[4];
                #pragma unroll
                for (int nt = 0; nt < 4; nt++) {
                    wmma::load_matrix_sync(bf[nt], &Ks[(warp * 64 + nt * 16) * 72 + ks], 72);
                }
                #pragma unroll
                for (int mt = 0; mt < 2; mt++) {
                    #pragma unroll
                    for (int nt = 0; nt < 4; nt++) {
                        wmma::mma_sync(sacc[mt][nt], af[mt], bf[nt], sacc[mt][nt]);
                    }
                }
            }
            #pragma unroll
            for (int mt = 0; mt < 2; mt++) {
                #pragma unroll
                for (int nt = 0; nt < 4; nt++) {
                    wmma::store_matrix_sync(&Ss[(mt * 16) * 520 + warp * 64 + nt * 16],
                                            sacc[mt][nt], 520, wmma::mem_row_major);
                }
            }
        }
        __syncthreads();

        /* softmax: warp w rows 4w..4w+3; write attn fp32, P fp16 aliased
           over the start of each fp32 S row (warp-private rows; the shfl
           reductions separate all reads from the aliased writes) */
        {
            float* attn_base = attn + ((long)bh * NSEQ + (long)chunk * 32) * NSEQ;
            #pragma unroll
            for (int rr = 0; rr < 4; rr++) {
                const int row = warp * 4 + rr;
                float v[16];
                float mx = -1e30f;
                #pragma unroll
                for (int j = 0; j < 16; j++) {
                    v[j] = Ss[row * 520 + lane + 32 * j] * 0.03125f;
                    mx = fmaxf(mx, v[j]);
                }
                #pragma unroll
                for (int o = 16; o > 0; o >>= 1) mx = fmaxf(mx, __shfl_xor_sync(0xffffffffu, mx, o));
                float sum = 0.f;
                #pragma unroll
                for (int j = 0; j < 16; j++) {
                    v[j] = expf(v[j] - mx);
                    sum += v[j];
                }
                #pragma unroll
                for (int o = 16; o > 0; o >>= 1) sum += __shfl_xor_sync(0xffffffffu, sum, o);
                const float inv = 1.0f / sum;
                __half* Pr = reinterpret_cast<__half*>(Ss + (size_t)row * 520);
                #pragma unroll
                for (int j = 0; j < 16; j++) {
                    const float e = v[j] * inv;
                    attn_base[(long)row * NSEQ + lane + 32 * j] = e;
                    Pr[lane + 32 * j] = __float2half(e);
                }
            }
        }
        __syncthreads();

        /* P @ V : warp (wm, wn) with wm = warp&1, wn = warp>>1 computes the
           16x16 output tile at rows wm*16, cols wn*16, full K depth */
        {
            const int wm = warp & 1;
            const int wn = warp >> 1;
            wmma::fragment<wmma::accumulator, 16, 16, 16, float> oacc;
            wmma::fill_fragment(oacc, 0.0f);
            const __half* Pbase = reinterpret_cast<const __half*>(Ss) + (wm * 16) * 1040;
            #pragma unroll
            for (int ks = 0; ks < 512; ks += 16) {
                wmma::fragment<wmma::matrix_a, 16, 16, 16, __half, wmma::row_major> af;
                wmma::load_matrix_sync(af, Pbase + ks, 1040);
                wmma::fragment<wmma::matrix_b, 16, 16, 16, __half, wmma::row_major> bf;
                wmma::load_matrix_sync(bf, &Vs[ks * 72 + wn * 16], 72);
                wmma::mma_sync(oacc, af, bf, oacc);
            }
            __syncthreads();
            /* stage 32 x 64 fp32 output (pitch 72) into the S region */
            float* stage = Ss;
            wmma::store_matrix_sync(&stage[(wm * 16) * 72 + wn * 16], oacc, 72,
                                    wmma::mem_row_major);
        }
        __syncthreads();

        /* ctx write: fp32 stage -> fp16 */
        {
            const int r = tid >> 3;
            const int c0 = (tid & 7) * 8;
            float a8[8];
            #pragma unroll
            for (int j = 0; j < 8; j++) a8[j] = Ss[r * 72 + c0 + j];
            __half2 hv[4];
            #pragma unroll
            for (int j = 0; j < 4; j++) hv[j] = __floats2half2_rn(a8[2 * j], a8[2 * j + 1]);
            __half* cp = ctx + (long)b * NSEQ * DIMC + (long)(chunk * 32 + r) * DIMC + h * 64 + c0;
            *reinterpret_cast<float4*>(cp) = *reinterpret_cast<float4*>(hv);
        }
        __syncthreads();
        if (chunk + 1 < 16) {
            __pipeline_wait_prior(0);
        }
    }
}

/* one pipeline stage load: A tile 128x32, B tile 32xBN.
   Bp is pre-offset to the block's column start. */
template<int BN>
__device__ __forceinline__ void load_stage(const __half* A, int lda,
                                           const __half* Bp, long ldbv,
                                           int brow, int k0,
                                           __half* As, __half* Bs, int tid) {
    const int AP  = 40;
    const int BPN = BN + 8;
    const int lr = tid >> 1;
    const int lc = (tid & 1) * 16;
    const __half* ga = A + (long)(brow + lr) * lda + k0 + lc;
    __pipeline_memcpy_async(&As[lr * AP + lc], ga, 16);
    __pipeline_memcpy_async(&As[lr * AP + lc + 8], ga + 8, 16);
    const int CH = BN / 8;
    #pragma unroll
    for (int q = 0; q < (32 * CH + 255) / 256; q++) {
        const int idx = tid + q * 256;
        if (idx < 32 * CH) {
            const int r = idx / CH;
            const int c = idx % CH;
            __pipeline_memcpy_async(&Bs[r * BPN + c * 8],
                                    Bp + (long)(k0 + r) * ldbv + c * 8, 16);
        }
    }
}

/*
 * WMMA tensor-core GEMM (NN). Block tile 128 x BN, K-step 32, 3-stage
 * cp.async pipeline. 8 warps as 4(m) x 2(n). F_FUSE: column blocks at or
 * beyond DIMC-PART read the per-batch expert weight B2/bias2 instead.
 */
template<int BN, int FLAGS>
__global__ __launch_bounds__(256, 2)
void hgemm(const __half* __restrict__ A, int lda,
           const __half* __restrict__ B, int ldb,
           float* __restrict__ Cf, __half* __restrict__ Ch, int ldc,
           int K,
           const float* __restrict__ bias,
           const float* __restrict__ res, int ldr,
           const int* __restrict__ indices, long wstride, int bstride,
           const __half* __restrict__ B2, int ldb2,
           const float* __restrict__ bias2)
{
    const int brow = blockIdx.y * 128;
    const int bcol = blockIdx.x * BN;

    const __half* Bp = B + bcol;
    const float* biasp = (FLAGS & F_BIAS) ? (bias + bcol) : bias;
    long ldbv = ldb;
    if ((FLAGS & F_FUSE) && bcol >= (DIMC - PART)) {
        const int idx = indices[brow >> 9];
        Bp    = B2 + (long)idx * wstride + (bcol - (DIMC - PART));
        biasp = bias2 + (long)idx * bstride + (bcol - (DIMC - PART));
        ldbv  = ldb2;
    }

    constexpr int AP  = 40;
    constexpr int BPN = BN + 8;
    constexpr int ASZ = 128 * AP;
    constexpr int BSZ = 32 * BPN;

    extern __shared__ __align__(16) char dyn[];
    __half* As = reinterpret_cast<__half*>(dyn);
    __half* Bs = As + 3 * ASZ;

    const int tid  = threadIdx.x;
    const int warp = tid >> 5;
    const int lane = tid & 31;
    const int wm = warp & 3;
    const int wn = warp >> 2;
    constexpr int NTF = BN / 32;

    wmma::fragment<wmma::accumulator, 16, 16, 16, float> acc[2][NTF];
    #pragma unroll
    for (int i = 0; i < 2; i++) {
        #pragma unroll
        for (int j = 0; j < NTF; j++) wmma::fill_fragment(acc[i][j], 0.0f);
    }

    const int iters = K >> 5;

    load_stage<BN>(A, lda, Bp, ldbv, brow, 0, As, Bs, tid);
    __pipeline_commit();
    if (iters > 1) {
        load_stage<BN>(A, lda, Bp, ldbv, brow, 32, As + ASZ, Bs + BSZ, tid);
        __pipeline_commit();
    }

    for (int it = 0; it < iters; ++it) {
        if (it + 1 < iters) {
            __pipeline_wait_prior(1);
        } else {
            __pipeline_wait_prior(0);
        }
        __syncthreads();
        if (it + 2 < iters) {
            const int ns = (it + 2) % 3;
            load_stage<BN>(A, lda, Bp, ldbv, brow, (it + 2) * 32,
                           As + ns * ASZ, Bs + ns * BSZ, tid);
            __pipeline_commit();
        }
        const int slot = it % 3;

        #pragma unroll
        for (int ks = 0; ks < 32; ks += 16) {
            wmma::fragment<wmma::matrix_a, 16, 16, 16, __half, wmma::row_major> af[2];
            #pragma unroll
            for (int mt = 0; mt < 2; mt++) {
                const __half* ap = &As[slot * ASZ + (wm * 32 + mt * 16) * AP + ks];
                wmma::load_matrix_sync(af[mt], ap, AP);
            }
            wmma::fragment<wmma::matrix_b, 16, 16, 16, __half, wmma::row_major> bf[NTF];
            #pragma unroll
            for (int nt = 0; nt < NTF; nt++) {
                const __half* bp = &Bs[slot * BSZ + ks * BPN + wn * (BN / 2) + nt * 16];
                wmma::load_matrix_sync(bf[nt], bp, BPN);
            }
            #pragma unroll
            for (int mt = 0; mt < 2; mt++) {
                #pragma unroll
                for (int nt = 0; nt < NTF; nt++) {
                    wmma::mma_sync(acc[mt][nt], af[mt], bf[nt], acc[mt][nt]);
                }
            }
        }
    }

    __syncthreads();

    /* epilogue: stage each 16x16 accumulator through smem */
    float* stage = reinterpret_cast<float*>(dyn) + warp * 16 * 20;
    const int er = lane >> 1;
    const int ec = (lane & 1) * 8;
    #pragma unroll
    for (int mt = 0; mt < 2; mt++) {
        #pragma unroll
        for (int nt = 0; nt < NTF; nt++) {
            wmma::store_matrix_sync(stage, acc[mt][nt], 20, wmma::mem_row_major);
            __syncwarp();
            const int row = brow + wm * 32 + mt * 16 + er;
            const int lcol = wn * (BN / 2) + nt * 16 + ec;
            const int col = bcol + lcol;
            float v[8];
            #pragma unroll
            for (int j = 0; j < 8; j++) v[j] = stage[er * 20 + ec + j];
            if (FLAGS & F_BIAS) {
                #pragma unroll
                for (int j = 0; j < 8; j++) v[j] += biasp[lcol + j];
            }
            if (FLAGS & F_GELU) {
                #pragma unroll
                for (int j = 0; j < 8; j++) v[j] = gelu_f(v[j]);
            }
            if (FLAGS & F_RES) {
                #pragma unroll
                for (int j = 0; j < 8; j++) v[j] += res[(long)row * ldr + col + j];
            }
            const long off = (long)row * ldc + col;
            if (FLAGS & F_OUTF) {
                float4 f0;
                f0.x = v[0]; f0.y = v[1]; f0.z = v[2]; f0.w = v[3];
                float4 f1;
                f1.x = v[4]; f1.y = v[5]; f1.z = v[6]; f1.w = v[7];
                *reinterpret_cast<float4*>(&Cf[off]) = f0;
                *reinterpret_cast<float4*>(&Cf[off + 4]) = f1;
            }
            if (FLAGS & F_OUTH) {
                __half2* hp = reinterpret_cast<__half2*>(&Ch[off]);
                hp[0] = __floats2half2_rn(v[0], v[1]);
                hp[1] = __floats2half2_rn(v[2], v[3]);
                hp[2] = __floats2half2_rn(v[4], v[5]);
                hp[3] = __floats2half2_rn(v[6], v[7]);
            }
            __syncwarp();
        }
    }
}

#define SMEM_NN128 (3 * (128 * 40 + 32 * 136) * 2)
#define SMEM_ATTN  223232

extern "C" void kernel_launch(void* const* d_in, const int* in_sizes, int n_in,
                              void* d_out, int out_size) {
    const float* x       = (const float*)d_in[0];
    const int*   indices = (const int*)  d_in[1];
    const float* ln1_w   = (const float*)d_in[2];
    const float* ln1_b   = (const float*)d_in[3];
    const float* qkv_w   = (const float*)d_in[4];
    const float* qkv_b   = (const float*)d_in[5];
    const float* out_w   = (const float*)d_in[6];
    const float* out_b   = (const float*)d_in[7];
    const float* ln2_w   = (const float*)d_in[8];
    const float* ln2_b   = (const float*)d_in[9];
    const float* fc1_w   = (const float*)d_in[10];
    const float* fc1_b   = (const float*)d_in[11];
    const float* fc2_w   = (const float*)d_in[12];
    const float* fc2_b   = (const float*)d_in[13];
    const float* exp_w   = (const float*)d_in[14];
    const float* exp_b   = (const float*)d_in[15];

    float* out_final = (float*)d_out;
    float* attn      = out_final + (size_t)TOK * DIMC;

    void* p;
    cudaGetSymbolAddress(&p, g_xn_h);
    __half* xn_h = (__half*)p;
    cudaGetSymbolAddress(&p, g_qkv_h);
    __half* qkv_h = (__half*)p;
    cudaGetSymbolAddress(&p, g_ctx_h);
    __half* ctx_h = (__half*)p;
    cudaGetSymbolAddress(&p, g_x1);
    float* x1 = (float*)p;
    cudaGetSymbolAddress(&p, g_h_h);
    __half* h_h = (__half*)p;
    cudaGetSymbolAddress(&p, g_qkvw_h);
    __half* qkvw_h = (__half*)p;
    cudaGetSymbolAddress(&p, g_outw_h);
    __half* outw_h = (__half*)p;
    cudaGetSymbolAddress(&p, g_fc1w_h);
    __half* fc1w_h = (__half*)p;
    cudaGetSymbolAddress(&p, g_fc2w_h);
    __half* fc2w_h = (__half*)p;
    cudaGetSymbolAddress(&p, g_expw_h);
    __half* expw_h = (__half*)p;

    cudaFuncSetAttribute(hgemm<128, F_BIAS | F_OUTH>,
                         cudaFuncAttributeMaxDynamicSharedMemorySize, SMEM_NN128);
    cudaFuncSetAttribute(hgemm<128, F_BIAS | F_RES | F_OUTF>,
                         cudaFuncAttributeMaxDynamicSharedMemorySize, SMEM_NN128);
    cudaFuncSetAttribute(hgemm<128, F_BIAS | F_GELU | F_OUTH>,
                         cudaFuncAttributeMaxDynamicSharedMemorySize, SMEM_NN128);
    cudaFuncSetAttribute(hgemm<128, F_BIAS | F_RES | F_OUTF | F_FUSE>,
                         cudaFuncAttributeMaxDynamicSharedMemorySize, SMEM_NN128);
    cudaFuncSetAttribute(attn_fused_k,
                         cudaFuncAttributeMaxDynamicSharedMemorySize, SMEM_ATTN);

    const int n0 = DIMC * 3 * DIMC / 4;
    const int n1 = DIMC * DIMC / 4;
    const int n2 = DIMC * MLPC / 4;
    const int n3 = MLPC * (DIMC - PART) / 4;
    const int n4 = 8 * MLPC * PART / 4;
    const int ntot = n0 + n1 + n2 + n3 + n4;
    cvt5_k<<<(ntot + 255) / 256, 256>>>(qkv_w, qkvw_h, n0,
                                        out_w, outw_h, n1,
                                        fc1_w, fc1w_h, n2,
                                        fc2_w, fc2w_h, n3,
                                        exp_w, expw_h, n4);

    layernorm_h_k<<<TOK, 256>>>(x, ln1_w, ln1_b, xn_h);

    hgemm<128, F_BIAS | F_OUTH><<<dim3(24, 32), 256, SMEM_NN128>>>(
        xn_h, DIMC, qkvw_h, 3 * DIMC, nullptr, qkv_h, 3 * DIMC, DIMC,
        qkv_b, nullptr, 0, nullptr, 0, 0, nullptr, 0, nullptr);

    attn_fused_k<<<dim3(128), 256, SMEM_ATTN>>>(qkv_h, attn, ctx_h);

    hgemm<128, F_BIAS | F_RES | F_OUTF><<<dim3(8, 32), 256, SMEM_NN128>>>(
        ctx_h, DIMC, outw_h, DIMC, x1, nullptr, DIMC, DIMC,
        out_b, x, DIMC, nullptr, 0, 0, nullptr, 0, nullptr);

    layernorm_h_k<<<TOK, 256>>>(x1, ln2_w, ln2_b, xn_h);

    hgemm<128, F_BIAS | F_GELU | F_OUTH><<<dim3(32, 32), 256, SMEM_NN128>>>(
        xn_h, DIMC, fc1w_h, MLPC, nullptr, h_h, MLPC, DIMC,
        fc1_b, nullptr, 0, nullptr, 0, 0, nullptr, 0, nullptr);

    hgemm<128, F_BIAS | F_RES | F_OUTF | F_FUSE><<<dim3(8, 32), 256, SMEM_NN128>>>(
        h_h, MLPC, fc2w_h, DIMC - PART, out_final, nullptr, DIMC, MLPC,
        fc2_b, x1, DIMC,
        indices, (long)MLPC * PART, PART,
        expw_h, PART, exp_b);
}